// round 2
// baseline (speedup 1.0000x reference)
#include <cuda_runtime.h>
#include <math.h>

#define HW 262144
#define CC 128
#define CQ 32
#define SP 256
#define NPART 148

// ---------------- scratch (device globals; no allocation allowed) -------------
__device__ float g_part[(size_t)NPART * SP * CC];   // per-block segment partials
__device__ int   g_icnts[SP];
__device__ float g_spmean[SP * CC];
__device__ float g_q[SP * CQ];
__device__ float g_k[SP * CQ];
__device__ float g_v[SP * CC];
__device__ float g_support[SP * CC];
__device__ float g_xpos[SP * CC];
__device__ float g_q2t[CQ * SP];                    // [j][s]
__device__ float g_v2[SP * CC];                     // [s][c]
__device__ float g_k2[(size_t)CQ * HW];             // [j][p]

// ---------------- small helpers ----------------------------------------------
__global__ void k_zero_cnts() {
    if (threadIdx.x < SP) g_icnts[threadIdx.x] = 0;
}

// histogram of labels (counts)
__global__ void k_hist(const int* __restrict__ sp) {
    __shared__ int h[SP];
    h[threadIdx.x] = 0;
    __syncthreads();
    int base = blockIdx.x * 1024;
#pragma unroll
    for (int k = 0; k < 4; ++k)
        atomicAdd(&h[sp[base + k * 256 + threadIdx.x]], 1);
    __syncthreads();
    atomicAdd(&g_icnts[threadIdx.x], h[threadIdx.x]);
}

// segment sums: channel-ownership (thread c owns channel c) -> no atomics
__global__ __launch_bounds__(256, 1) void k_segsum(const float* __restrict__ x,
                                                   const int* __restrict__ sp) {
    extern __shared__ float sm[];
    float* bins = sm;                 // SP*CC = 32768 floats
    float* xs   = sm + SP * CC;       // 128*129 floats (padded)
    __shared__ int lab[128];
    int tid = threadIdx.x;

    for (int i = tid; i < SP * CC; i += 256) bins[i] = 0.f;

    for (int tile = blockIdx.x; tile < HW / 128; tile += NPART) {
        int pb = tile * 128;
        __syncthreads();              // protect lab/xs reuse + bins init
        if (tid < 128) lab[tid] = sp[pb + tid];
        for (int idx = tid; idx < 128 * 128; idx += 256) {
            int c = idx >> 7, p = idx & 127;
            xs[p * 129 + c] = x[(size_t)c * HW + pb + p];
        }
        __syncthreads();
        if (tid < 128) {
#pragma unroll 4
            for (int p = 0; p < 128; ++p) {
                bins[lab[p] * CC + tid] += xs[p * 129 + tid];
            }
        }
    }
    __syncthreads();
    float* dst = g_part + (size_t)blockIdx.x * (SP * CC);
    for (int i = tid; i < SP * CC; i += 256) dst[i] = bins[i];
}

// reduce partials -> spmean
__global__ void k_mean() {
    int i = blockIdx.x * 256 + threadIdx.x;   // < 32768
    int s = i >> 7;
    float sum = 0.f;
#pragma unroll 4
    for (int b = 0; b < NPART; ++b) sum += g_part[(size_t)b * (SP * CC) + i];
    float cnt = fmaxf((float)g_icnts[s], 1.f);
    g_spmean[i] = sum / cnt;
}

// q,k,v from spmean
__global__ void k_qkv(const float* __restrict__ wq, const float* __restrict__ bq,
                      const float* __restrict__ wk, const float* __restrict__ bk,
                      const float* __restrict__ wv, const float* __restrict__ bv) {
    __shared__ float row[CC];
    int s = blockIdx.x, t = threadIdx.x;   // 128 threads
    row[t] = g_spmean[s * CC + t];
    __syncthreads();
    float a = 0.f;
    const float* wr = wv + t * CC;
#pragma unroll 8
    for (int i = 0; i < CC; ++i) a += row[i] * wr[i];
    g_v[s * CC + t] = a + bv[t];
    if (t < CQ) {
        float aq = 0.f, ak = 0.f;
        const float* wqr = wq + t * CC;
        const float* wkr = wk + t * CC;
#pragma unroll 8
        for (int i = 0; i < CC; ++i) { aq += row[i] * wqr[i]; ak += row[i] * wkr[i]; }
        g_q[s * CQ + t] = aq + bq[t];
        g_k[s * CQ + t] = ak + bk[t];
    }
}

// support = v @ gcn_weight
__global__ void k_support(const float* __restrict__ gw) {
    __shared__ float row[CC];
    int s = blockIdx.x, t = threadIdx.x;   // 128 threads
    row[t] = g_v[s * CC + t];
    __syncthreads();
    float a = 0.f;
#pragma unroll 8
    for (int i = 0; i < CC; ++i) a += row[i] * gw[i * CC + t];
    g_support[s * CC + t] = a;
}

// adj row softmax + xpos = adj @ support + bias
__global__ void k_adj_xpos(const float* __restrict__ gbias) {
    __shared__ float kr[CQ];
    __shared__ float w[SP];
    __shared__ float red[SP];
    int s = blockIdx.x, t = threadIdx.x;   // 256 threads
    if (t < CQ) kr[t] = g_k[s * CQ + t];
    __syncthreads();
    float lg = 0.f;
    const float* qr = g_q + t * CQ;
#pragma unroll
    for (int i = 0; i < CQ; ++i) lg += kr[i] * qr[i];
    red[t] = lg;
    __syncthreads();
    for (int off = 128; off > 0; off >>= 1) {
        if (t < off) red[t] = fmaxf(red[t], red[t + off]);
        __syncthreads();
    }
    float m = red[0];
    __syncthreads();
    float e = __expf(lg - m);
    red[t] = e;
    __syncthreads();
    for (int off = 128; off > 0; off >>= 1) {
        if (t < off) red[t] += red[t + off];
        __syncthreads();
    }
    float inv = 1.f / red[0];
    w[t] = e * inv;
    __syncthreads();
    if (t < CC) {
        float a = 0.f;
#pragma unroll 4
        for (int j = 0; j < SP; ++j) a += w[j] * g_support[j * CC + t];
        g_xpos[s * CC + t] = a + gbias[t];
    }
}

// q2 (transposed layout) and v2 from xpos
__global__ void k_q2v2(const float* __restrict__ wq, const float* __restrict__ bq,
                       const float* __restrict__ wv, const float* __restrict__ bv) {
    __shared__ float row[CC];
    int s = blockIdx.x, t = threadIdx.x;   // 128 threads
    row[t] = g_xpos[s * CC + t];
    __syncthreads();
    float a = 0.f;
    const float* wr = wv + t * CC;
#pragma unroll 8
    for (int i = 0; i < CC; ++i) a += row[i] * wr[i];
    g_v2[s * CC + t] = a + bv[t];
    if (t < CQ) {
        float aq = 0.f;
        const float* wqr = wq + t * CC;
#pragma unroll 8
        for (int i = 0; i < CC; ++i) aq += row[i] * wqr[i];
        g_q2t[t * SP + s] = aq + bq[t];
    }
}

// k2[j][p] = sum_c x[c][p] * a_wk[j][c] + a_bk[j]
// Also (flag) writes the x passthrough to out2 = out + CC*HW, fused with the
// x read so the passthrough costs no extra HBM read.
__global__ __launch_bounds__(256, 2) void k_k2(const float* __restrict__ x,
                                               const float* __restrict__ wk,
                                               const float* __restrict__ bk,
                                               float* __restrict__ out2,
                                               int do_copy) {
    extern __shared__ float sm[];
    float* xs  = sm;              // 128*128
    float* wkt = sm + 128 * 128;  // [c][j] 128*32
    int tid = threadIdx.x;        // 256
    int pb = blockIdx.x * 128;

    for (int idx = tid; idx < CC * CQ; idx += 256) {
        int c = idx >> 5, j = idx & 31;
        wkt[c * CQ + j] = wk[j * CC + c];
    }
    for (int idx = tid; idx < CC * 128; idx += 256) {
        int c = idx >> 7, p = idx & 127;
        float v = x[(size_t)c * HW + pb + p];
        xs[c * 128 + p] = v;
        if (do_copy) out2[(size_t)c * HW + pb + p] = v;
    }
    __syncthreads();

    int pg = tid >> 3, jg = tid & 7;
    int p0 = pg * 4, j0 = jg * 4;
    float acc[4][4];
#pragma unroll
    for (int i = 0; i < 4; ++i)
#pragma unroll
        for (int j = 0; j < 4; ++j) acc[i][j] = 0.f;

#pragma unroll 4
    for (int c = 0; c < CC; ++c) {
        float4 xv = *(const float4*)(xs + c * 128 + p0);
        float4 wv = *(const float4*)(wkt + c * CQ + j0);
        float xa[4] = {xv.x, xv.y, xv.z, xv.w};
        float wa[4] = {wv.x, wv.y, wv.z, wv.w};
#pragma unroll
        for (int i = 0; i < 4; ++i)
#pragma unroll
            for (int j = 0; j < 4; ++j) acc[i][j] += xa[i] * wa[j];
    }
#pragma unroll
    for (int j = 0; j < 4; ++j) {
        float b = bk[j0 + j];
        float4 o = make_float4(acc[0][j] + b, acc[1][j] + b, acc[2][j] + b, acc[3][j] + b);
        *(float4*)(g_k2 + (size_t)(j0 + j) * HW + pb + p0) = o;
    }
}

// big kernel: logits -> softmax(unnormalized) -> out = atten @ v2 (FFMA2),
// row normalization folded into the epilogue.
__global__ __launch_bounds__(256, 1) void k_atten_out(float* __restrict__ out) {
    extern __shared__ float sm[];
    float* A   = sm;            // 16384 floats: phase1 q2s/k2s, later w[s][p] (swizzled)
    float* v2s = sm + 16384;    // 32768 floats [s][c]
    float* q2s = A;             // [cc][256]
    float* k2s = A + 8192;      // [cc][64]
    __shared__ float sinv[64];  // per-pixel 1/sum
    int tid = threadIdx.x;      // 256
    int pbase = blockIdx.x * 64;

    for (int i = tid; i < CQ * SP; i += 256) q2s[i] = g_q2t[i];
    for (int i = tid; i < CQ * 64; i += 256) {
        int cc = i >> 6, p = i & 63;
        k2s[cc * 64 + p] = g_k2[(size_t)cc * HW + pbase + p];
    }
    for (int i = tid; i < SP * CC; i += 256) v2s[i] = g_v2[i];
    __syncthreads();

    // --- logits: warp wg owns pixels wg*8..+7; lane owns s = lane*8..+7
    int wg = tid >> 5, lane = tid & 31;
    int p0 = wg * 8, s0 = lane * 8;
    float lg[8][8];
#pragma unroll
    for (int i = 0; i < 8; ++i)
#pragma unroll
        for (int j = 0; j < 8; ++j) lg[i][j] = 0.f;

#pragma unroll 4
    for (int cc = 0; cc < CQ; ++cc) {
        float4 ka = *(const float4*)(k2s + cc * 64 + p0);
        float4 kb = *(const float4*)(k2s + cc * 64 + p0 + 4);
        float4 qa = *(const float4*)(q2s + cc * SP + s0);
        float4 qb = *(const float4*)(q2s + cc * SP + s0 + 4);
        float kk[8] = {ka.x, ka.y, ka.z, ka.w, kb.x, kb.y, kb.z, kb.w};
        float qq[8] = {qa.x, qa.y, qa.z, qa.w, qb.x, qb.y, qb.z, qb.w};
#pragma unroll
        for (int pi = 0; pi < 8; ++pi)
#pragma unroll
            for (int si = 0; si < 8; ++si) lg[pi][si] += kk[pi] * qq[si];
    }
    __syncthreads();    // everyone done reading q2s/k2s (region A)

    // --- store logits into w (region A), XOR-swizzled to kill bank conflicts
#pragma unroll
    for (int si = 0; si < 8; ++si) {
        int s = s0 + si;
        int ks = (s >> 3) & 15;
#pragma unroll
        for (int pi = 0; pi < 8; ++pi) {
            int p = p0 + pi;
            A[s * 64 + (((p >> 2) ^ ks) << 2) + (p & 3)] = lg[pi][si];
        }
    }
    __syncthreads();

    // --- softmax (unnormalized) per pixel: 4 threads/pixel, 64 s each.
    // Store exp(l - m) back in place; keep 1/sum in sinv[p].
    {
        int p = tid >> 2, q = tid & 3;
        int pg = p >> 2, pr = p & 3;
        float m = -1e30f;
#pragma unroll
        for (int i = 0; i < 64; ++i) {
            int s = q * 64 + i;
            m = fmaxf(m, A[s * 64 + ((pg ^ ((s >> 3) & 15)) << 2) + pr]);
        }
        m = fmaxf(m, __shfl_xor_sync(0xffffffffu, m, 1));
        m = fmaxf(m, __shfl_xor_sync(0xffffffffu, m, 2));
        float ssum = 0.f;
#pragma unroll
        for (int i = 0; i < 64; ++i) {
            int s = q * 64 + i;
            int idx = s * 64 + ((pg ^ ((s >> 3) & 15)) << 2) + pr;
            float e = __expf(A[idx] - m);
            A[idx] = e;
            ssum += e;
        }
        ssum += __shfl_xor_sync(0xffffffffu, ssum, 1);
        ssum += __shfl_xor_sync(0xffffffffu, ssum, 2);
        if (q == 0) sinv[p] = 1.f / ssum;
    }
    __syncthreads();

    // --- out[c][p] = (sum_s w[p][s] * v2[s][c]) * sinv[p], FFMA2 over ch pairs
    int cg = tid & 15, pg2 = tid >> 4;
    int c0 = cg * 8;
    int q0 = pg2 * 4;
    unsigned long long acc[4][4];
#pragma unroll
    for (int i = 0; i < 4; ++i)
#pragma unroll
        for (int j = 0; j < 4; ++j) acc[i][j] = 0ULL;

#pragma unroll 2
    for (int s = 0; s < SP; ++s) {
        ulonglong2 va = *(const ulonglong2*)(v2s + s * CC + c0);
        ulonglong2 vb = *(const ulonglong2*)(v2s + s * CC + c0 + 4);
        float4 wv = *(const float4*)(A + s * 64 + ((pg2 ^ ((s >> 3) & 15)) << 2));
        float wa[4] = {wv.x, wv.y, wv.z, wv.w};
#pragma unroll
        for (int pi = 0; pi < 4; ++pi) {
            unsigned long long wp;
            asm("mov.b64 %0, {%1, %1};" : "=l"(wp) : "f"(wa[pi]));
            asm("fma.rn.f32x2 %0, %1, %2, %0;" : "+l"(acc[0][pi]) : "l"(va.x), "l"(wp));
            asm("fma.rn.f32x2 %0, %1, %2, %0;" : "+l"(acc[1][pi]) : "l"(va.y), "l"(wp));
            asm("fma.rn.f32x2 %0, %1, %2, %0;" : "+l"(acc[2][pi]) : "l"(vb.x), "l"(wp));
            asm("fma.rn.f32x2 %0, %1, %2, %0;" : "+l"(acc[3][pi]) : "l"(vb.y), "l"(wp));
        }
    }

    float pscale[4];
#pragma unroll
    for (int pi = 0; pi < 4; ++pi) pscale[pi] = sinv[q0 + pi];

#pragma unroll
    for (int ci2 = 0; ci2 < 4; ++ci2) {
        float lo[4], hi[4];
#pragma unroll
        for (int pi = 0; pi < 4; ++pi) {
            asm("mov.b64 {%0, %1}, %2;" : "=f"(lo[pi]), "=f"(hi[pi]) : "l"(acc[ci2][pi]));
            lo[pi] *= pscale[pi];
            hi[pi] *= pscale[pi];
        }
        int c = c0 + ci2 * 2;
        *(float4*)(out + (size_t)c * HW + pbase + q0) =
            make_float4(lo[0], lo[1], lo[2], lo[3]);
        *(float4*)(out + (size_t)(c + 1) * HW + pbase + q0) =
            make_float4(hi[0], hi[1], hi[2], hi[3]);
    }
}

// -----------------------------------------------------------------------------
extern "C" void kernel_launch(void* const* d_in, const int* in_sizes, int n_in,
                              void* d_out, int out_size) {
    const float* x   = (const float*)d_in[0];
    const int*   sp  = (const int*)d_in[1];
    const float* gw  = (const float*)d_in[2];
    const float* gb  = (const float*)d_in[3];
    const float* gwq = (const float*)d_in[4];
    const float* gbq = (const float*)d_in[5];
    const float* gwk = (const float*)d_in[6];
    const float* gbk = (const float*)d_in[7];
    const float* gwv = (const float*)d_in[8];
    const float* gbv = (const float*)d_in[9];
    const float* awq = (const float*)d_in[10];
    const float* abq = (const float*)d_in[11];
    const float* awk = (const float*)d_in[12];
    const float* abk = (const float*)d_in[13];
    const float* awv = (const float*)d_in[14];
    const float* abv = (const float*)d_in[15];
    float* out = (float*)d_out;

    cudaFuncSetAttribute(k_segsum, cudaFuncAttributeMaxDynamicSharedMemorySize, 197120);
    cudaFuncSetAttribute(k_k2, cudaFuncAttributeMaxDynamicSharedMemorySize, 81920);
    cudaFuncSetAttribute(k_atten_out, cudaFuncAttributeMaxDynamicSharedMemorySize, 196608);

    int do_copy = (out_size >= 2 * CC * HW) ? 1 : 0;

    k_zero_cnts<<<1, 256>>>();
    k_hist<<<256, 256>>>(sp);
    k_segsum<<<NPART, 256, 197120>>>(x, sp);
    k_mean<<<128, 256>>>();
    k_qkv<<<SP, 128>>>(gwq, gbq, gwk, gbk, gwv, gbv);
    k_support<<<SP, 128>>>(gw);
    k_adj_xpos<<<SP, 256>>>(gb);
    k_q2v2<<<SP, 128>>>(awq, abq, awv, abv);
    k_k2<<<HW / 128, 256, 81920>>>(x, awk, abk, out + (size_t)CC * HW, do_copy);
    k_atten_out<<<HW / 64, 256, 196608>>>(out);
}

// round 5
// speedup vs baseline: 1.1852x; 1.1852x over previous
#include <cuda_runtime.h>
#include <math.h>

#define HW 262144
#define CC 128
#define CQ 32
#define SP 256
#define NPART 148

// ---------------- scratch (device globals; no allocation allowed) -------------
__device__ float g_part[(size_t)NPART * SP * CC];   // per-block segment partials
__device__ float g_cntp[(size_t)NPART * SP];        // per-block label counts
__device__ float g_spmean[SP * CC];
__device__ float g_q[SP * CQ];
__device__ float g_k[SP * CQ];
__device__ float g_support[SP * CC];
__device__ float g_q2t[CQ * SP];                    // [j][s]
__device__ float g_v2[SP * CC];                     // [s][c]
__device__ float g_k2[(size_t)CQ * HW];             // [j][p]

// segment sums: channel-ownership (thread c owns channel c) -> no atomics.
// Upper 128 threads count labels (2 labels each) during the accumulate phase.
__global__ __launch_bounds__(256, 1) void k_segsum(const float* __restrict__ x,
                                                   const int* __restrict__ sp) {
    extern __shared__ float sm[];
    float* bins = sm;                 // SP*CC = 32768 floats
    float* xs   = sm + SP * CC;       // 128*129 floats (padded)
    __shared__ int lab[128];
    int tid = threadIdx.x;

    for (int i = tid; i < SP * CC; i += 256) bins[i] = 0.f;

    int cnt0 = 0, cnt1 = 0;
    int mylab = tid - 128;            // labels owned by counting threads

    for (int tile = blockIdx.x; tile < HW / 128; tile += NPART) {
        int pb = tile * 128;
        __syncthreads();              // protect lab/xs reuse + bins init
        if (tid < 128) lab[tid] = sp[pb + tid];
        for (int idx = tid; idx < 128 * 128; idx += 256) {
            int c = idx >> 7, p = idx & 127;
            xs[p * 129 + c] = x[(size_t)c * HW + pb + p];
        }
        __syncthreads();
        if (tid < 128) {
#pragma unroll 4
            for (int p = 0; p < 128; ++p) {
                bins[lab[p] * CC + tid] += xs[p * 129 + tid];
            }
        } else {
#pragma unroll 4
            for (int p = 0; p < 128; ++p) {
                int l = lab[p];
                cnt0 += (l == mylab);
                cnt1 += (l == mylab + 128);
            }
        }
    }
    __syncthreads();
    float* dst = g_part + (size_t)blockIdx.x * (SP * CC);
    for (int i = tid; i < SP * CC; i += 256) dst[i] = bins[i];
    if (tid >= 128) {
        g_cntp[blockIdx.x * SP + mylab]       = (float)cnt0;
        g_cntp[blockIdx.x * SP + mylab + 128] = (float)cnt1;
    }
}

// reduce partials -> spmean. Block b covers i in [b*256, b*256+256) -> s in {2b, 2b+1}
__global__ void k_mean() {
    __shared__ float scnt[2];
    int t = threadIdx.x;
    int s0 = 2 * blockIdx.x;
    if (t < 2) {
        float c = 0.f;
#pragma unroll 8
        for (int bpart = 0; bpart < NPART; ++bpart)
            c += g_cntp[bpart * SP + s0 + t];
        scnt[t] = fmaxf(c, 1.f);
    }
    int i = blockIdx.x * 256 + t;   // < 32768
    float sum = 0.f;
#pragma unroll 8
    for (int bpart = 0; bpart < NPART; ++bpart) sum += g_part[(size_t)bpart * (SP * CC) + i];
    __syncthreads();
    g_spmean[i] = sum / scnt[t >> 7];
}

// q,k,v,support for one node (fused)
__global__ void k_node1(const float* __restrict__ wq, const float* __restrict__ bq,
                        const float* __restrict__ wk, const float* __restrict__ bk,
                        const float* __restrict__ wv, const float* __restrict__ bv,
                        const float* __restrict__ gw) {
    __shared__ float row[CC];
    __shared__ float vsh[CC];
    int s = blockIdx.x, t = threadIdx.x;   // 128 threads
    row[t] = g_spmean[s * CC + t];
    __syncthreads();
    float a = 0.f;
    const float* wr = wv + t * CC;
#pragma unroll 8
    for (int i = 0; i < CC; ++i) a += row[i] * wr[i];
    vsh[t] = a + bv[t];
    if (t < CQ) {
        float aq = 0.f, ak = 0.f;
        const float* wqr = wq + t * CC;
        const float* wkr = wk + t * CC;
#pragma unroll 8
        for (int i = 0; i < CC; ++i) { aq += row[i] * wqr[i]; ak += row[i] * wkr[i]; }
        g_q[s * CQ + t] = aq + bq[t];
        g_k[s * CQ + t] = ak + bk[t];
    }
    __syncthreads();
    float b = 0.f;
#pragma unroll 8
    for (int i = 0; i < CC; ++i) b += vsh[i] * gw[i * CC + t];
    g_support[s * CC + t] = b;
}

// adj row softmax + xpos + q2/v2 (fused)
__global__ void k_node2(const float* __restrict__ gbias,
                        const float* __restrict__ awq, const float* __restrict__ abq,
                        const float* __restrict__ awv, const float* __restrict__ abv) {
    __shared__ float kr[CQ];
    __shared__ float w[SP];
    __shared__ float red[SP];
    __shared__ float xr[CC];
    int s = blockIdx.x, t = threadIdx.x;   // 256 threads
    if (t < CQ) kr[t] = g_k[s * CQ + t];
    __syncthreads();
    float lg = 0.f;
    const float* qr = g_q + t * CQ;
#pragma unroll
    for (int i = 0; i < CQ; ++i) lg += kr[i] * qr[i];
    red[t] = lg;
    __syncthreads();
    for (int off = 128; off > 0; off >>= 1) {
        if (t < off) red[t] = fmaxf(red[t], red[t + off]);
        __syncthreads();
    }
    float m = red[0];
    __syncthreads();
    float e = __expf(lg - m);
    red[t] = e;
    __syncthreads();
    for (int off = 128; off > 0; off >>= 1) {
        if (t < off) red[t] += red[t + off];
        __syncthreads();
    }
    float inv = 1.f / red[0];
    w[t] = e * inv;
    __syncthreads();
    if (t < CC) {
        float a = 0.f;
#pragma unroll 4
        for (int j = 0; j < SP; ++j) a += w[j] * g_support[j * CC + t];
        xr[t] = a + gbias[t];
    }
    __syncthreads();
    if (t < CC) {
        float a = 0.f;
        const float* wr = awv + t * CC;
#pragma unroll 8
        for (int i = 0; i < CC; ++i) a += xr[i] * wr[i];
        g_v2[s * CC + t] = a + abv[t];
    } else if (t < 128 + CQ) {
        int j = t - 128;
        float aq = 0.f;
        const float* wqr = awq + j * CC;
#pragma unroll 8
        for (int i = 0; i < CC; ++i) aq += xr[i] * wqr[i];
        g_q2t[j * SP + s] = aq + abq[j];
    }
}

// k2[j][p] = sum_c x[c][p] * a_wk[j][c] + a_bk[j]
// Also (flag) writes the x passthrough to out2 = out + CC*HW, fused with the
// x read so the passthrough costs no extra HBM read.
__global__ __launch_bounds__(256, 2) void k_k2(const float* __restrict__ x,
                                               const float* __restrict__ wk,
                                               const float* __restrict__ bk,
                                               float* __restrict__ out2,
                                               int do_copy) {
    extern __shared__ float sm[];
    float* xs  = sm;              // 128*128
    float* wkt = sm + 128 * 128;  // [c][j] 128*32
    int tid = threadIdx.x;        // 256
    int pb = blockIdx.x * 128;

    for (int idx = tid; idx < CC * CQ; idx += 256) {
        int c = idx >> 5, j = idx & 31;
        wkt[c * CQ + j] = wk[j * CC + c];
    }
    for (int idx = tid; idx < CC * 128; idx += 256) {
        int c = idx >> 7, p = idx & 127;
        float v = x[(size_t)c * HW + pb + p];
        xs[c * 128 + p] = v;
        if (do_copy) out2[(size_t)c * HW + pb + p] = v;
    }
    __syncthreads();

    int pg = tid >> 3, jg = tid & 7;
    int p0 = pg * 4, j0 = jg * 4;
    float acc[4][4];
#pragma unroll
    for (int i = 0; i < 4; ++i)
#pragma unroll
        for (int j = 0; j < 4; ++j) acc[i][j] = 0.f;

#pragma unroll 4
    for (int c = 0; c < CC; ++c) {
        float4 xv = *(const float4*)(xs + c * 128 + p0);
        float4 wv = *(const float4*)(wkt + c * CQ + j0);
        float xa[4] = {xv.x, xv.y, xv.z, xv.w};
        float wa[4] = {wv.x, wv.y, wv.z, wv.w};
#pragma unroll
        for (int i = 0; i < 4; ++i)
#pragma unroll
            for (int j = 0; j < 4; ++j) acc[i][j] += xa[i] * wa[j];
    }
#pragma unroll
    for (int j = 0; j < 4; ++j) {
        float b = bk[j0 + j];
        float4 o = make_float4(acc[0][j] + b, acc[1][j] + b, acc[2][j] + b, acc[3][j] + b);
        *(float4*)(g_k2 + (size_t)(j0 + j) * HW + pb + p0) = o;
    }
}

// big kernel: logits (f32x2) -> softmax(unnormalized) -> out = atten @ v2 (f32x2,
// v2 read from L2 via LDG). 64 KB smem -> occupancy 2.
__global__ __launch_bounds__(256, 2) void k_atten_out(float* __restrict__ out) {
    extern __shared__ float sm[];
    float* A   = sm;            // 16384 floats: phase1 q2s/k2s, later w[s][p] (swizzled)
    float* q2s = A;             // [cc][256]
    float* k2s = A + 8192;      // [cc][64]
    __shared__ float sinv[64];  // per-pixel 1/sum
    int tid = threadIdx.x;      // 256
    int pbase = blockIdx.x * 64;

    for (int i = tid; i < CQ * SP; i += 256) q2s[i] = g_q2t[i];
    for (int i = tid; i < CQ * 64; i += 256) {
        int cc = i >> 6, p = i & 63;
        k2s[cc * 64 + p] = g_k2[(size_t)cc * HW + pbase + p];
    }
    __syncthreads();

    // --- logits: warp wg owns pixels wg*8..+7; lane owns s = lane*8..+7 (4 f32x2 pairs)
    int wg = tid >> 5, lane = tid & 31;
    int p0 = wg * 8, s0 = lane * 8;
    unsigned long long lacc[8][4];
#pragma unroll
    for (int i = 0; i < 8; ++i)
#pragma unroll
        for (int j = 0; j < 4; ++j) lacc[i][j] = 0ULL;

#pragma unroll 4
    for (int cc = 0; cc < CQ; ++cc) {
        float4 ka = *(const float4*)(k2s + cc * 64 + p0);
        float4 kb = *(const float4*)(k2s + cc * 64 + p0 + 4);
        ulonglong2 qa = *(const ulonglong2*)(q2s + cc * SP + s0);
        ulonglong2 qb = *(const ulonglong2*)(q2s + cc * SP + s0 + 4);
        float kk[8] = {ka.x, ka.y, ka.z, ka.w, kb.x, kb.y, kb.z, kb.w};
        unsigned long long qq[4] = {qa.x, qa.y, qb.x, qb.y};
#pragma unroll
        for (int pi = 0; pi < 8; ++pi) {
            unsigned long long kp;
            asm("mov.b64 %0, {%1, %1};" : "=l"(kp) : "f"(kk[pi]));
#pragma unroll
            for (int sj = 0; sj < 4; ++sj)
                asm("fma.rn.f32x2 %0, %1, %2, %0;" : "+l"(lacc[pi][sj]) : "l"(qq[sj]), "l"(kp));
        }
    }
    __syncthreads();    // everyone done reading q2s/k2s (region A)

    // --- store logits into w (region A), XOR-swizzled to kill bank conflicts
#pragma unroll
    for (int pi = 0; pi < 8; ++pi) {
        int p = p0 + pi;
        int pw = p & 3, pgw = p >> 2;
#pragma unroll
        for (int sj = 0; sj < 4; ++sj) {
            float lo, hi;
            asm("mov.b64 {%0, %1}, %2;" : "=f"(lo), "=f"(hi) : "l"(lacc[pi][sj]));
            int se = s0 + 2 * sj, so = se + 1;
            A[se * 64 + ((pgw ^ ((se >> 3) & 15)) << 2) + pw] = lo;
            A[so * 64 + ((pgw ^ ((so >> 3) & 15)) << 2) + pw] = hi;
        }
    }
    __syncthreads();

    // --- softmax (unnormalized) per pixel: 4 threads/pixel, 64 s each.
    {
        int p = tid >> 2, q = tid & 3;
        int pg = p >> 2, pr = p & 3;
        float m = -1e30f;
#pragma unroll
        for (int i = 0; i < 64; ++i) {
            int s = q * 64 + i;
            m = fmaxf(m, A[s * 64 + ((pg ^ ((s >> 3) & 15)) << 2) + pr]);
        }
        m = fmaxf(m, __shfl_xor_sync(0xffffffffu, m, 1));
        m = fmaxf(m, __shfl_xor_sync(0xffffffffu, m, 2));
        float ssum = 0.f;
#pragma unroll
        for (int i = 0; i < 64; ++i) {
            int s = q * 64 + i;
            int idx = s * 64 + ((pg ^ ((s >> 3) & 15)) << 2) + pr;
            float e = __expf(A[idx] - m);
            A[idx] = e;
            ssum += e;
        }
        ssum += __shfl_xor_sync(0xffffffffu, ssum, 1);
        ssum += __shfl_xor_sync(0xffffffffu, ssum, 2);
        if (q == 0) sinv[p] = 1.f / ssum;
    }
    __syncthreads();

    // --- out[c][p] = (sum_s w[p][s] * v2[s][c]) * sinv[p]; v2 via LDG (L2-hot)
    int cg = tid & 15, pg2 = tid >> 4;
    int c0 = cg * 8;
    int q0 = pg2 * 4;
    unsigned long long acc[4][4];
#pragma unroll
    for (int i = 0; i < 4; ++i)
#pragma unroll
        for (int j = 0; j < 4; ++j) acc[i][j] = 0ULL;

    const float* v2p = g_v2;
#pragma unroll 2
    for (int s = 0; s < SP; ++s) {
        ulonglong2 va = *(const ulonglong2*)(v2p + s * CC + c0);
        ulonglong2 vb = *(const ulonglong2*)(v2p + s * CC + c0 + 4);
        float4 wv = *(const float4*)(A + s * 64 + ((pg2 ^ ((s >> 3) & 15)) << 2));
        float wa[4] = {wv.x, wv.y, wv.z, wv.w};
#pragma unroll
        for (int pi = 0; pi < 4; ++pi) {
            unsigned long long wp;
            asm("mov.b64 %0, {%1, %1};" : "=l"(wp) : "f"(wa[pi]));
            asm("fma.rn.f32x2 %0, %1, %2, %0;" : "+l"(acc[0][pi]) : "l"(va.x), "l"(wp));
            asm("fma.rn.f32x2 %0, %1, %2, %0;" : "+l"(acc[1][pi]) : "l"(va.y), "l"(wp));
            asm("fma.rn.f32x2 %0, %1, %2, %0;" : "+l"(acc[2][pi]) : "l"(vb.x), "l"(wp));
            asm("fma.rn.f32x2 %0, %1, %2, %0;" : "+l"(acc[3][pi]) : "l"(vb.y), "l"(wp));
        }
    }

    float pscale[4];
#pragma unroll
    for (int pi = 0; pi < 4; ++pi) pscale[pi] = sinv[q0 + pi];

#pragma unroll
    for (int ci2 = 0; ci2 < 4; ++ci2) {
        float lo[4], hi[4];
#pragma unroll
        for (int pi = 0; pi < 4; ++pi) {
            asm("mov.b64 {%0, %1}, %2;" : "=f"(lo[pi]), "=f"(hi[pi]) : "l"(acc[ci2][pi]));
            lo[pi] *= pscale[pi];
            hi[pi] *= pscale[pi];
        }
        int c = c0 + ci2 * 2;
        *(float4*)(out + (size_t)c * HW + pbase + q0) =
            make_float4(lo[0], lo[1], lo[2], lo[3]);
        *(float4*)(out + (size_t)(c + 1) * HW + pbase + q0) =
            make_float4(hi[0], hi[1], hi[2], hi[3]);
    }
}

// -----------------------------------------------------------------------------
extern "C" void kernel_launch(void* const* d_in, const int* in_sizes, int n_in,
                              void* d_out, int out_size) {
    const float* x   = (const float*)d_in[0];
    const int*   sp  = (const int*)d_in[1];
    const float* gw  = (const float*)d_in[2];
    const float* gb  = (const float*)d_in[3];
    const float* gwq = (const float*)d_in[4];
    const float* gbq = (const float*)d_in[5];
    const float* gwk = (const float*)d_in[6];
    const float* gbk = (const float*)d_in[7];
    const float* gwv = (const float*)d_in[8];
    const float* gbv = (const float*)d_in[9];
    const float* awq = (const float*)d_in[10];
    const float* abq = (const float*)d_in[11];
    const float* awk = (const float*)d_in[12];
    const float* abk = (const float*)d_in[13];
    const float* awv = (const float*)d_in[14];
    const float* abv = (const float*)d_in[15];
    float* out = (float*)d_out;

    cudaFuncSetAttribute(k_segsum, cudaFuncAttributeMaxDynamicSharedMemorySize, 197120);
    cudaFuncSetAttribute(k_k2, cudaFuncAttributeMaxDynamicSharedMemorySize, 81920);
    cudaFuncSetAttribute(k_atten_out, cudaFuncAttributeMaxDynamicSharedMemorySize, 65536);

    int do_copy = (out_size >= 2 * CC * HW) ? 1 : 0;

    k_segsum<<<NPART, 256, 197120>>>(x, sp);
    k_mean<<<128, 256>>>();
    k_node1<<<SP, 128>>>(gwq, gbq, gwk, gbk, gwv, gbv, gw);
    k_node2<<<SP, 256>>>(gb, awq, abq, awv, abv);
    k_k2<<<HW / 128, 256, 81920>>>(x, awk, abk, out + (size_t)CC * HW, do_copy);
    k_atten_out<<<HW / 64, 256, 65536>>>(out);
}

// round 8
// speedup vs baseline: 1.2807x; 1.0806x over previous
#include <cuda_runtime.h>
#include <math.h>

#define HW 262144
#define CC 128
#define CQ 32
#define SP 256
#define NPART 148

// ---------------- scratch (device globals; no allocation allowed) -------------
__device__ float g_part[(size_t)NPART * SP * CC];   // per-block segment partials
__device__ float g_cntp[(size_t)NPART * SP];        // per-block label counts
__device__ float g_spmean[SP * CC];
__device__ float g_qT[CQ * SP];                     // [j][s]
__device__ float g_k[SP * CQ];
__device__ float g_support[SP * CC];
__device__ float g_q2t[CQ * SP];                    // [j][s]
__device__ float g_v2[SP * CC];                     // [s][c]
__device__ float g_k2[(size_t)CQ * HW];             // [j][p]
// transposed weights ([in][out] layout for coalesced per-output-channel loads)
__device__ float g_wvT[CC * CC];
__device__ float g_wqT[CC * CQ];
__device__ float g_wkT[CC * CQ];
__device__ float g_awvT[CC * CC];
__device__ float g_awqT[CC * CQ];

// transpose the 5 weight matrices once (tiny)
__global__ void k_prep(const float* __restrict__ wq, const float* __restrict__ wk,
                       const float* __restrict__ wv, const float* __restrict__ awq,
                       const float* __restrict__ awv) {
    int idx = blockIdx.x * 256 + threadIdx.x;   // < 16384
    int o = idx >> 7, i = idx & 127;            // o<128, i<128
    g_wvT[i * CC + o]  = wv[o * CC + i];
    g_awvT[i * CC + o] = awv[o * CC + i];
    if (o < CQ) {
        g_wqT[i * CQ + o]  = wq[o * CC + i];
        g_wkT[i * CQ + o]  = wk[o * CC + i];
        g_awqT[i * CQ + o] = awq[o * CC + i];
    }
}

// segment sums: channel-ownership (thread c owns channel c) -> no atomics.
// Upper 128 threads count labels (2 labels each) during the accumulate phase.
__global__ __launch_bounds__(256, 1) void k_segsum(const float* __restrict__ x,
                                                   const int* __restrict__ sp) {
    extern __shared__ float sm[];
    float* bins = sm;                 // SP*CC = 32768 floats
    float* xs   = sm + SP * CC;       // 128*129 floats (padded)
    __shared__ int lab[128];
    int tid = threadIdx.x;

    for (int i = tid; i < SP * CC; i += 256) bins[i] = 0.f;

    int cnt0 = 0, cnt1 = 0;
    int mylab = tid - 128;            // labels owned by counting threads

    for (int tile = blockIdx.x; tile < HW / 128; tile += NPART) {
        int pb = tile * 128;
        __syncthreads();              // protect lab/xs reuse + bins init
        if (tid < 128) lab[tid] = sp[pb + tid];
        for (int idx = tid; idx < 128 * 128; idx += 256) {
            int c = idx >> 7, p = idx & 127;
            xs[p * 129 + c] = x[(size_t)c * HW + pb + p];
        }
        __syncthreads();
        if (tid < 128) {
#pragma unroll 4
            for (int p = 0; p < 128; ++p) {
                bins[lab[p] * CC + tid] += xs[p * 129 + tid];
            }
        } else {
#pragma unroll 4
            for (int p = 0; p < 128; ++p) {
                int l = lab[p];
                cnt0 += (l == mylab);
                cnt1 += (l == mylab + 128);
            }
        }
    }
    __syncthreads();
    float* dst = g_part + (size_t)blockIdx.x * (SP * CC);
    for (int i = tid; i < SP * CC; i += 256) dst[i] = bins[i];
    if (tid >= 128) {
        g_cntp[blockIdx.x * SP + mylab]       = (float)cnt0;
        g_cntp[blockIdx.x * SP + mylab + 128] = (float)cnt1;
    }
}

// reduce partials -> spmean. 1024 threads: 4 quarter-range partial sums per i.
__global__ __launch_bounds__(1024) void k_mean() {
    __shared__ float part[1024];
    __shared__ float cpart[4][2];
    int t = threadIdx.x & 255, q = threadIdx.x >> 8;
    int i = blockIdx.x * 256 + t;   // < 32768
    int b0 = q * 37, b1 = b0 + 37;  // 148 = 4*37
    float sum = 0.f;
#pragma unroll 8
    for (int b = b0; b < b1; ++b) sum += g_part[(size_t)b * (SP * CC) + i];
    part[q * 256 + t] = sum;
    if (t < 2) {
        float c = 0.f;
        for (int b = b0; b < b1; ++b) c += g_cntp[b * SP + 2 * blockIdx.x + t];
        cpart[q][t] = c;
    }
    __syncthreads();
    if (q == 0) {
        float tot = part[t] + part[256 + t] + part[512 + t] + part[768 + t];
        float cnt = fmaxf(cpart[0][t >> 7] + cpart[1][t >> 7] +
                          cpart[2][t >> 7] + cpart[3][t >> 7], 1.f);
        g_spmean[i] = tot / cnt;
    }
}

// q,k,v,support for one node (fused, transposed-weight coalesced loads)
__global__ void k_node1(const float* __restrict__ bq, const float* __restrict__ bk,
                        const float* __restrict__ bv, const float* __restrict__ gw) {
    __shared__ float row[CC];
    __shared__ float vsh[CC];
    int s = blockIdx.x, t = threadIdx.x;   // 128 threads
    row[t] = g_spmean[s * CC + t];
    __syncthreads();
    float a = 0.f;
#pragma unroll 8
    for (int i = 0; i < CC; ++i) a += row[i] * g_wvT[i * CC + t];
    vsh[t] = a + bv[t];
    if (t < CQ) {
        float aq = 0.f, ak = 0.f;
#pragma unroll 8
        for (int i = 0; i < CC; ++i) { aq += row[i] * g_wqT[i * CQ + t]; ak += row[i] * g_wkT[i * CQ + t]; }
        g_qT[t * SP + s] = aq + bq[t];
        g_k[s * CQ + t]  = ak + bk[t];
    }
    __syncthreads();
    float b = 0.f;
#pragma unroll 8
    for (int i = 0; i < CC; ++i) b += vsh[i] * gw[i * CC + t];
    g_support[s * CC + t] = b;
}

// adj row softmax + xpos + q2/v2 (fused, coalesced loads)
__global__ void k_node2(const float* __restrict__ gbias,
                        const float* __restrict__ abq, const float* __restrict__ abv) {
    __shared__ float kr[CQ];
    __shared__ float w[SP];
    __shared__ float red[SP];
    __shared__ float xr[CC];
    int s = blockIdx.x, t = threadIdx.x;   // 256 threads
    if (t < CQ) kr[t] = g_k[s * CQ + t];
    __syncthreads();
    float lg = 0.f;
#pragma unroll
    for (int i = 0; i < CQ; ++i) lg += kr[i] * g_qT[i * SP + t];
    red[t] = lg;
    __syncthreads();
    for (int off = 128; off > 0; off >>= 1) {
        if (t < off) red[t] = fmaxf(red[t], red[t + off]);
        __syncthreads();
    }
    float m = red[0];
    __syncthreads();
    float e = __expf(lg - m);
    red[t] = e;
    __syncthreads();
    for (int off = 128; off > 0; off >>= 1) {
        if (t < off) red[t] += red[t + off];
        __syncthreads();
    }
    float inv = 1.f / red[0];
    w[t] = e * inv;
    __syncthreads();
    if (t < CC) {
        float a = 0.f;
#pragma unroll 8
        for (int j = 0; j < SP; ++j) a += w[j] * g_support[j * CC + t];
        xr[t] = a + gbias[t];
    }
    __syncthreads();
    if (t < CC) {
        float a = 0.f;
#pragma unroll 8
        for (int i = 0; i < CC; ++i) a += xr[i] * g_awvT[i * CC + t];
        g_v2[s * CC + t] = a + abv[t];
    } else if (t < 128 + CQ) {
        int j = t - 128;
        float aq = 0.f;
#pragma unroll 8
        for (int i = 0; i < CC; ++i) aq += xr[i] * g_awqT[i * CQ + j];
        g_q2t[j * SP + s] = aq + abq[j];
    }
}

// k2[j][p] = sum_c x[c][p] * a_wk[j][c] + a_bk[j]  (f32x2 over p-pairs)
// Also (flag) writes the x passthrough to out2 = out + CC*HW, fused with the
// x read so the passthrough costs no extra HBM read.
__global__ __launch_bounds__(256, 2) void k_k2(const float* __restrict__ x,
                                               const float* __restrict__ wk,
                                               const float* __restrict__ bk,
                                               float* __restrict__ out2,
                                               int do_copy) {
    extern __shared__ float sm[];
    float* xs  = sm;              // 128*128
    float* wkt = sm + 128 * 128;  // [c][j] 128*32
    int tid = threadIdx.x;        // 256
    int pb = blockIdx.x * 128;

    for (int idx = tid; idx < CC * CQ; idx += 256) {
        int c = idx >> 5, j = idx & 31;
        wkt[c * CQ + j] = wk[j * CC + c];
    }
    for (int idx = tid; idx < CC * 128; idx += 256) {
        int c = idx >> 7, p = idx & 127;
        float v = x[(size_t)c * HW + pb + p];
        xs[c * 128 + p] = v;
        if (do_copy) out2[(size_t)c * HW + pb + p] = v;
    }
    __syncthreads();

    int pg = tid >> 3, jg = tid & 7;
    int p0 = pg * 4, j0 = jg * 4;
    // acc2[pp][j]: f32x2 accumulator for p-pair pp (p0+2pp, p0+2pp+1), output j0+j
    unsigned long long acc2[2][4];
#pragma unroll
    for (int i = 0; i < 2; ++i)
#pragma unroll
        for (int j = 0; j < 4; ++j) acc2[i][j] = 0ULL;

#pragma unroll 4
    for (int c = 0; c < CC; ++c) {
        ulonglong2 xv = *(const ulonglong2*)(xs + c * 128 + p0);   // 2 f32x2 pairs
        float4 wv = *(const float4*)(wkt + c * CQ + j0);
        unsigned long long xp[2] = {xv.x, xv.y};
        float wa[4] = {wv.x, wv.y, wv.z, wv.w};
#pragma unroll
        for (int j = 0; j < 4; ++j) {
            unsigned long long wp;
            asm("mov.b64 %0, {%1, %1};" : "=l"(wp) : "f"(wa[j]));
            asm("fma.rn.f32x2 %0, %1, %2, %0;" : "+l"(acc2[0][j]) : "l"(xp[0]), "l"(wp));
            asm("fma.rn.f32x2 %0, %1, %2, %0;" : "+l"(acc2[1][j]) : "l"(xp[1]), "l"(wp));
        }
    }
#pragma unroll
    for (int j = 0; j < 4; ++j) {
        float b = bk[j0 + j];
        float a0, a1, a2, a3;
        asm("mov.b64 {%0, %1}, %2;" : "=f"(a0), "=f"(a1) : "l"(acc2[0][j]));
        asm("mov.b64 {%0, %1}, %2;" : "=f"(a2), "=f"(a3) : "l"(acc2[1][j]));
        float4 o = make_float4(a0 + b, a1 + b, a2 + b, a3 + b);
        *(float4*)(g_k2 + (size_t)(j0 + j) * HW + pb + p0) = o;
    }
}

// big kernel: logits (f32x2) -> softmax(unnormalized) -> out = atten @ v2 (f32x2,
// v2 staged in shared in 4 s-chunks of 32KB). 96 KB smem -> occupancy 2.
__global__ __launch_bounds__(256, 2) void k_atten_out(float* __restrict__ out) {
    extern __shared__ float sm[];
    float* A   = sm;            // 16384 floats: phase1 q2s/k2s, later w[s][p] (swizzled)
    float* v2s = sm + 16384;    // 8192 floats: v2 chunk [64 s][128 c]
    float* q2s = A;             // [cc][256]
    float* k2s = A + 8192;      // [cc][64]
    __shared__ float sinv[64];  // per-pixel 1/sum
    int tid = threadIdx.x;      // 256
    int pbase = blockIdx.x * 64;

    for (int i = tid; i < CQ * SP; i += 256) q2s[i] = g_q2t[i];
    for (int i = tid; i < CQ * 64; i += 256) {
        int cc = i >> 6, p = i & 63;
        k2s[cc * 64 + p] = g_k2[(size_t)cc * HW + pbase + p];
    }
    __syncthreads();

    // --- logits: warp wg owns pixels wg*8..+7; lane owns s = lane*8..+7 (4 f32x2 pairs)
    int wg = tid >> 5, lane = tid & 31;
    int p0 = wg * 8, s0 = lane * 8;
    unsigned long long lacc[8][4];
#pragma unroll
    for (int i = 0; i < 8; ++i)
#pragma unroll
        for (int j = 0; j < 4; ++j) lacc[i][j] = 0ULL;

#pragma unroll 4
    for (int cc = 0; cc < CQ; ++cc) {
        float4 ka = *(const float4*)(k2s + cc * 64 + p0);
        float4 kb = *(const float4*)(k2s + cc * 64 + p0 + 4);
        ulonglong2 qa = *(const ulonglong2*)(q2s + cc * SP + s0);
        ulonglong2 qb = *(const ulonglong2*)(q2s + cc * SP + s0 + 4);
        float kk[8] = {ka.x, ka.y, ka.z, ka.w, kb.x, kb.y, kb.z, kb.w};
        unsigned long long qq[4] = {qa.x, qa.y, qb.x, qb.y};
#pragma unroll
        for (int pi = 0; pi < 8; ++pi) {
            unsigned long long kp;
            asm("mov.b64 %0, {%1, %1};" : "=l"(kp) : "f"(kk[pi]));
#pragma unroll
            for (int sj = 0; sj < 4; ++sj)
                asm("fma.rn.f32x2 %0, %1, %2, %0;" : "+l"(lacc[pi][sj]) : "l"(qq[sj]), "l"(kp));
        }
    }
    __syncthreads();    // everyone done reading q2s/k2s (region A)

    // --- store logits into w (region A), XOR-swizzled to kill bank conflicts
#pragma unroll
    for (int pi = 0; pi < 8; ++pi) {
        int p = p0 + pi;
        int pw = p & 3, pgw = p >> 2;
#pragma unroll
        for (int sj = 0; sj < 4; ++sj) {
            float lo, hi;
            asm("mov.b64 {%0, %1}, %2;" : "=f"(lo), "=f"(hi) : "l"(lacc[pi][sj]));
            int se = s0 + 2 * sj, so = se + 1;
            A[se * 64 + ((pgw ^ ((se >> 3) & 15)) << 2) + pw] = lo;
            A[so * 64 + ((pgw ^ ((so >> 3) & 15)) << 2) + pw] = hi;
        }
    }
    __syncthreads();

    // --- softmax (unnormalized) per pixel: 4 threads/pixel, 64 s each.
    {
        int p = tid >> 2, q = tid & 3;
        int pg = p >> 2, pr = p & 3;
        float m = -1e30f;
#pragma unroll
        for (int i = 0; i < 64; ++i) {
            int s = q * 64 + i;
            m = fmaxf(m, A[s * 64 + ((pg ^ ((s >> 3) & 15)) << 2) + pr]);
        }
        m = fmaxf(m, __shfl_xor_sync(0xffffffffu, m, 1));
        m = fmaxf(m, __shfl_xor_sync(0xffffffffu, m, 2));
        float ssum = 0.f;
#pragma unroll
        for (int i = 0; i < 64; ++i) {
            int s = q * 64 + i;
            int idx = s * 64 + ((pg ^ ((s >> 3) & 15)) << 2) + pr;
            float e = __expf(A[idx] - m);
            A[idx] = e;
            ssum += e;
        }
        ssum += __shfl_xor_sync(0xffffffffu, ssum, 1);
        ssum += __shfl_xor_sync(0xffffffffu, ssum, 2);
        if (q == 0) sinv[p] = 1.f / ssum;
    }

    // --- out[c][p] = (sum_s w[p][s] * v2[s][c]) * sinv[p]; v2 via 4 smem chunks
    int cg = tid & 15, pg2 = tid >> 4;
    int c0 = cg * 8;
    int q0 = pg2 * 4;
    unsigned long long acc[4][4];
#pragma unroll
    for (int i = 0; i < 4; ++i)
#pragma unroll
        for (int j = 0; j < 4; ++j) acc[i][j] = 0ULL;

#pragma unroll
    for (int sc = 0; sc < 4; ++sc) {
        __syncthreads();            // previous chunk consumed (1st: softmax done)
        // load v2 chunk [64 s][128 c] = 2048 float4, coalesced
        {
            const float4* src = (const float4*)(g_v2 + sc * 64 * CC);
            float4* dst = (float4*)v2s;
#pragma unroll
            for (int i = 0; i < 8; ++i) dst[tid + i * 256] = src[tid + i * 256];
        }
        __syncthreads();
#pragma unroll 2
        for (int sl = 0; sl < 64; ++sl) {
            int s = sc * 64 + sl;
            ulonglong2 va = *(const ulonglong2*)(v2s + sl * CC + c0);
            ulonglong2 vb = *(const ulonglong2*)(v2s + sl * CC + c0 + 4);
            float4 wv = *(const float4*)(A + s * 64 + ((pg2 ^ ((s >> 3) & 15)) << 2));
            float wa[4] = {wv.x, wv.y, wv.z, wv.w};
#pragma unroll
            for (int pi = 0; pi < 4; ++pi) {
                unsigned long long wp;
                asm("mov.b64 %0, {%1, %1};" : "=l"(wp) : "f"(wa[pi]));
                asm("fma.rn.f32x2 %0, %1, %2, %0;" : "+l"(acc[0][pi]) : "l"(va.x), "l"(wp));
                asm("fma.rn.f32x2 %0, %1, %2, %0;" : "+l"(acc[1][pi]) : "l"(va.y), "l"(wp));
                asm("fma.rn.f32x2 %0, %1, %2, %0;" : "+l"(acc[2][pi]) : "l"(vb.x), "l"(wp));
                asm("fma.rn.f32x2 %0, %1, %2, %0;" : "+l"(acc[3][pi]) : "l"(vb.y), "l"(wp));
            }
        }
    }

    float pscale[4];
#pragma unroll
    for (int pi = 0; pi < 4; ++pi) pscale[pi] = sinv[q0 + pi];

#pragma unroll
    for (int ci2 = 0; ci2 < 4; ++ci2) {
        float lo[4], hi[4];
#pragma unroll
        for (int pi = 0; pi < 4; ++pi) {
            asm("mov.b64 {%0, %1}, %2;" : "=f"(lo[pi]), "=f"(hi[pi]) : "l"(acc[ci2][pi]));
            lo[pi] *= pscale[pi];
            hi[pi] *= pscale[pi];
        }
        int c = c0 + ci2 * 2;
        *(float4*)(out + (size_t)c * HW + pbase + q0) =
            make_float4(lo[0], lo[1], lo[2], lo[3]);
        *(float4*)(out + (size_t)(c + 1) * HW + pbase + q0) =
            make_float4(hi[0], hi[1], hi[2], hi[3]);
    }
}

// -----------------------------------------------------------------------------
extern "C" void kernel_launch(void* const* d_in, const int* in_sizes, int n_in,
                              void* d_out, int out_size) {
    const float* x   = (const float*)d_in[0];
    const int*   sp  = (const int*)d_in[1];
    const float* gw  = (const float*)d_in[2];
    const float* gb  = (const float*)d_in[3];
    const float* gwq = (const float*)d_in[4];
    const float* gbq = (const float*)d_in[5];
    const float* gwk = (const float*)d_in[6];
    const float* gbk = (const float*)d_in[7];
    const float* gwv = (const float*)d_in[8];
    const float* gbv = (const float*)d_in[9];
    const float* awq = (const float*)d_in[10];
    const float* abq = (const float*)d_in[11];
    const float* awk = (const float*)d_in[12];
    const float* abk = (const float*)d_in[13];
    const float* awv = (const float*)d_in[14];
    const float* abv = (const float*)d_in[15];
    float* out = (float*)d_out;

    cudaFuncSetAttribute(k_segsum, cudaFuncAttributeMaxDynamicSharedMemorySize, 197120);
    cudaFuncSetAttribute(k_k2, cudaFuncAttributeMaxDynamicSharedMemorySize, 81920);
    cudaFuncSetAttribute(k_atten_out, cudaFuncAttributeMaxDynamicSharedMemorySize, 98304);

    int do_copy = (out_size >= 2 * CC * HW) ? 1 : 0;

    k_prep<<<64, 256>>>(gwq, gwk, gwv, awq, awv);
    k_segsum<<<NPART, 256, 197120>>>(x, sp);
    k_mean<<<128, 1024>>>();
    k_node1<<<SP, 128>>>(gbq, gbk, gbv, gw);
    k_node2<<<SP, 256>>>(gb, abq, abv);
    k_k2<<<HW / 128, 256, 81920>>>(x, awk, abk, out + (size_t)CC * HW, do_copy);
    k_atten_out<<<HW / 64, 256, 98304>>>(out);
}